// round 16
// baseline (speedup 1.0000x reference)
#include <cuda_runtime.h>
#include <cuda_bf16.h>
#include <cuda_fp16.h>
#include <cstdint>
#include <math.h>

#define N_NODES 50000
#define N_EDGES 600000
#define D 128
#define N_IDX 4096
#define NB 196              // ceil(50000/256) blocks per edge type

// ---------------- scratch (static device allocations; no cudaMalloc) -------
__device__ __half g_Hh[3][N_NODES * D];   // per-branch layer-1 GEMM outputs (fp16)
__device__ __half g_Hcur[N_NODES * D];    // layer-1 combined features (fp16)
__device__ float g_A2[3][N_IDX * D];      // layer-2 aggregated inputs
__device__ float g_O2[3][N_IDX * D];      // layer-2 GEMM outputs
__device__ float g_dinv[3][N_NODES];
__device__ int   g_counts[3][N_NODES];
__device__ int   g_rowptr[3][N_NODES + 1];
__device__ int   g_cursor[3][N_NODES];
__device__ int   g_col[3][N_EDGES];
__device__ int   g_bsum[3][NB];

// ---------------- CSR build -------------------------------------------------
__global__ void init_counts_kernel() {
    int i = blockIdx.x * blockDim.x + threadIdx.x;
    if (i < 3 * N_NODES) ((int*)g_counts)[i] = 0;
}

__global__ void count_deg_kernel(const int* __restrict__ e0,
                                 const int* __restrict__ e1,
                                 const int* __restrict__ e2) {
    int idx = blockIdx.x * blockDim.x + threadIdx.x;
    if (idx >= 3 * N_EDGES) return;
    int t = idx / N_EDGES;
    int e = idx - t * N_EDGES;
    const int* ep = (t == 0) ? e0 : (t == 1) ? e1 : e2;
    atomicAdd(&g_counts[t][ep[N_EDGES + e]], 1);
}

// pass 1: per-block sums of counts
__global__ void partial_sums_kernel() {
    int t   = blockIdx.x / NB;
    int blk = blockIdx.x % NB;
    int i   = blk * 256 + threadIdx.x;
    int v   = (i < N_NODES) ? g_counts[t][i] : 0;
    __shared__ int sh[256];
    sh[threadIdx.x] = v;
    __syncthreads();
    #pragma unroll
    for (int off = 128; off > 0; off >>= 1) {
        if (threadIdx.x < off) sh[threadIdx.x] += sh[threadIdx.x + off];
        __syncthreads();
    }
    if (threadIdx.x == 0) g_bsum[t][blk] = sh[0];
}

// pass 2: each block computes its own offset, in-block scan -> rowptr/cursor/dinv
__global__ void rowptr_final_kernel() {
    int t   = blockIdx.x / NB;
    int blk = blockIdx.x % NB;
    int i   = blk * 256 + threadIdx.x;
    int v   = (i < N_NODES) ? g_counts[t][i] : 0;

    __shared__ int sh[256];
    __shared__ int red[256];

    int p = 0;
    for (int q = threadIdx.x; q < blk; q += 256) p += g_bsum[t][q];
    red[threadIdx.x] = p;
    sh[threadIdx.x] = v;
    __syncthreads();
    #pragma unroll
    for (int off = 128; off > 0; off >>= 1) {
        if (threadIdx.x < off) red[threadIdx.x] += red[threadIdx.x + off];
        __syncthreads();
    }
    int boff = red[0];

    #pragma unroll
    for (int off = 1; off < 256; off <<= 1) {
        int add = (threadIdx.x >= off) ? sh[threadIdx.x - off] : 0;
        __syncthreads();
        sh[threadIdx.x] += add;
        __syncthreads();
    }
    if (i < N_NODES) {
        int excl = boff + sh[threadIdx.x] - v;
        g_rowptr[t][i] = excl;
        g_cursor[t][i] = excl;
        g_dinv[t][i]   = rsqrtf((float)(v + 1));   // +1 self loop
    }
    if (blk == NB - 1 && threadIdx.x == 255) g_rowptr[t][N_NODES] = boff + sh[255];
}

__global__ void scatter_edges_kernel(const int* __restrict__ e0,
                                     const int* __restrict__ e1,
                                     const int* __restrict__ e2) {
    int idx = blockIdx.x * blockDim.x + threadIdx.x;
    if (idx >= 3 * N_EDGES) return;
    int t = idx / N_EDGES;
    int e = idx - t * N_EDGES;
    const int* ep = (t == 0) ? e0 : (t == 1) ? e1 : e2;
    int src = ep[e];
    int dst = ep[N_EDGES + e];
    int pos = atomicAdd(&g_cursor[t][dst], 1);
    g_col[t][pos] = src;
}

// ---------------- bf16 hi/lo split -------------------------------------------
__device__ __forceinline__ void split_bf16(float v, __nv_bfloat16& h, __nv_bfloat16& l) {
    h = __float2bfloat16(v);
    l = __float2bfloat16(v - __bfloat162float(h));
}

// ---------------- tensor-core GEMM: g_Hh[t] = X @ W[t] (bf16 split) ---------
// BOTH X and W conversions fused: loads fp32, splits hi/lo in registers to smem.
__device__ __forceinline__ void ldsm_x4(unsigned* r, unsigned addr) {
    asm volatile("ldmatrix.sync.aligned.m8n8.x4.shared.b16 {%0,%1,%2,%3}, [%4];"
                 : "=r"(r[0]), "=r"(r[1]), "=r"(r[2]), "=r"(r[3]) : "r"(addr));
}
__device__ __forceinline__ void ldsm_x2t(unsigned* r, unsigned addr) {
    asm volatile("ldmatrix.sync.aligned.m8n8.x2.trans.shared.b16 {%0,%1}, [%2];"
                 : "=r"(r[0]), "=r"(r[1]) : "r"(addr));
}
__device__ __forceinline__ void mma_bf16(float* c, const unsigned* a, const unsigned* b) {
    asm volatile(
        "mma.sync.aligned.m16n8k16.row.col.f32.bf16.bf16.f32 "
        "{%0,%1,%2,%3}, {%4,%5,%6,%7}, {%8,%9}, {%0,%1,%2,%3};"
        : "+f"(c[0]), "+f"(c[1]), "+f"(c[2]), "+f"(c[3])
        : "r"(a[0]), "r"(a[1]), "r"(a[2]), "r"(a[3]), "r"(b[0]), "r"(b[1]));
}

__device__ __forceinline__ void split8_to_chunks(float4 va, float4 vb,
                                                 uint4& hp_out, uint4& lp_out) {
    __nv_bfloat16 h0,h1,h2,h3,h4,h5,h6,h7, l0,l1,l2,l3,l4,l5,l6,l7;
    split_bf16(va.x, h0, l0); split_bf16(va.y, h1, l1);
    split_bf16(va.z, h2, l2); split_bf16(va.w, h3, l3);
    split_bf16(vb.x, h4, l4); split_bf16(vb.y, h5, l5);
    split_bf16(vb.z, h6, l6); split_bf16(vb.w, h7, l7);
    __nv_bfloat162 hp[4] = { __halves2bfloat162(h0,h1), __halves2bfloat162(h2,h3),
                             __halves2bfloat162(h4,h5), __halves2bfloat162(h6,h7) };
    __nv_bfloat162 lp[4] = { __halves2bfloat162(l0,l1), __halves2bfloat162(l2,l3),
                             __halves2bfloat162(l4,l5), __halves2bfloat162(l6,l7) };
    hp_out = *(uint4*)hp;
    lp_out = *(uint4*)lp;
}

__global__ __launch_bounds__(256) void mma_gemm_kernel(const float* __restrict__ X,
                                                       const float* __restrict__ w0,
                                                       const float* __restrict__ w1,
                                                       const float* __restrict__ w2,
                                                       int M) {
    int t = blockIdx.y;
    const float* W = (t == 0) ? w0 : (t == 1) ? w1 : w2;
    __half* Hout = g_Hh[t];

    __shared__ __align__(16) unsigned char sA[128 * 128];
    __shared__ __align__(16) unsigned char sB[2][32 * 256];

    int tid = threadIdx.x;
    int lane = tid & 31, wid = tid >> 5;
    int wm = wid >> 2;
    int wn = wid & 3;
    int row0 = blockIdx.x * 128;

    unsigned sA_u  = (unsigned)__cvta_generic_to_shared(sA);
    unsigned sBh_u = (unsigned)__cvta_generic_to_shared(sB[0]);
    unsigned sBl_u = (unsigned)__cvta_generic_to_shared(sB[1]);

    float c[4][4][4];
    #pragma unroll
    for (int i = 0; i < 4; i++)
        #pragma unroll
        for (int j = 0; j < 4; j++)
            #pragma unroll
            for (int q = 0; q < 4; q++) c[i][j][q] = 0.f;

    for (int kc = 0; kc < 4; kc++) {
        // fused A load+convert: 512 tasks = row x col-group; hi chunk q, lo chunk q+4
        #pragma unroll
        for (int i = 0; i < 2; i++) {
            int cid = tid + i * 256;           // 0..511
            int r = cid >> 2, q = cid & 3;     // row 0..127, col-group 0..3
            int gr = row0 + r;
            float4 va = make_float4(0.f, 0.f, 0.f, 0.f);
            float4 vb = make_float4(0.f, 0.f, 0.f, 0.f);
            if (gr < M) {
                const float* xp = X + (size_t)gr * D + kc * 32 + q * 8;
                va = *(const float4*)xp;
                vb = *(const float4*)(xp + 4);
            }
            uint4 hp, lp;
            split8_to_chunks(va, vb, hp, lp);
            *(uint4*)(sA + r * 128 + ((q ^ (r & 7)) << 4))       = hp;
            *(uint4*)(sA + r * 128 + (((q + 4) ^ (r & 7)) << 4)) = lp;
        }
        // fused B load+convert: 512 tasks = k-row x chunk; fp32 W -> hi/lo buffers
        #pragma unroll
        for (int i = 0; i < 2; i++) {
            int cid = tid + i * 256;           // 0..511
            int k = cid >> 4, ch = cid & 15;   // k-row 0..31, chunk 0..15
            const float* wp = W + (size_t)(kc * 32 + k) * D + ch * 8;
            float4 va = *(const float4*)wp;
            float4 vb = *(const float4*)(wp + 4);
            uint4 hp, lp;
            split8_to_chunks(va, vb, hp, lp);
            unsigned off = k * 256 + ((ch ^ (k & 7)) << 4);
            *(uint4*)(sB[0] + off) = hp;
            *(uint4*)(sB[1] + off) = lp;
        }
        __syncthreads();

        #pragma unroll
        for (int ks = 0; ks < 2; ks++) {
            unsigned ah[4][4], al[4][4], bh[4][2], bl[4][2];
            #pragma unroll
            for (int mf = 0; mf < 4; mf++) {
                int mr = wm * 64 + mf * 16 + (lane & 7) + ((lane >> 3) & 1) * 8;
                int lc = ks * 2 + (lane >> 4);
                ldsm_x4(ah[mf], sA_u + mr * 128 + ((lc ^ (mr & 7)) << 4));
                ldsm_x4(al[mf], sA_u + mr * 128 + (((lc + 4) ^ (mr & 7)) << 4));
            }
            #pragma unroll
            for (int nf = 0; nf < 4; nf++) {
                int kk = ks * 16 + (lane & 7) + ((lane >> 3) & 1) * 8;
                int gc = wn * 4 + nf;
                unsigned off = kk * 256 + ((gc ^ (kk & 7)) << 4);
                ldsm_x2t(bh[nf], sBh_u + off);
                ldsm_x2t(bl[nf], sBl_u + off);
            }
            #pragma unroll
            for (int mf = 0; mf < 4; mf++)
                #pragma unroll
                for (int nf = 0; nf < 4; nf++) {
                    mma_bf16(c[mf][nf], ah[mf], bh[nf]);
                    mma_bf16(c[mf][nf], ah[mf], bl[nf]);
                    mma_bf16(c[mf][nf], al[mf], bh[nf]);
                }
        }
        __syncthreads();
    }

    // store accumulators as fp16
    int g = lane >> 2, tq = lane & 3;
    #pragma unroll
    for (int mf = 0; mf < 4; mf++) {
        int r0 = row0 + wm * 64 + mf * 16 + g;
        int r1 = r0 + 8;
        #pragma unroll
        for (int nf = 0; nf < 4; nf++) {
            int cb = wn * 32 + nf * 8 + tq * 2;
            if (r0 < M) *(__half2*)(Hout + (size_t)r0 * D + cb) = __floats2half2_rn(c[mf][nf][0], c[mf][nf][1]);
            if (r1 < M) *(__half2*)(Hout + (size_t)r1 * D + cb) = __floats2half2_rn(c[mf][nf][2], c[mf][nf][3]);
        }
    }
}

// ---------------- FFMA GEMM for small layer-2 matrices (per-branch grid.y) --
__global__ void gemm_small_kernel(const float* __restrict__ w0,
                                  const float* __restrict__ w1,
                                  const float* __restrict__ w2, int M) {
    int t = blockIdx.y;
    const float* X = g_A2[t];
    const float* W = (t == 0) ? w0 : (t == 1) ? w1 : w2;
    float* Hout = g_O2[t];

    __shared__ float As[8][128];
    __shared__ float Bs[8][128];

    int tid  = threadIdx.x;
    int row0 = blockIdx.x * 128;
    int tx = tid & 15;
    int ty = tid >> 4;

    float acc[8][8];
    #pragma unroll
    for (int i = 0; i < 8; i++)
        #pragma unroll
        for (int j = 0; j < 8; j++) acc[i][j] = 0.f;

    for (int k0 = 0; k0 < 128; k0 += 8) {
        {
            int m  = tid >> 1;
            int kk = (tid & 1) * 4;
            int gr = row0 + m;
            float4 v = make_float4(0.f, 0.f, 0.f, 0.f);
            if (gr < M) v = *(const float4*)(X + gr * D + k0 + kk);
            As[kk + 0][m] = v.x;
            As[kk + 1][m] = v.y;
            As[kk + 2][m] = v.z;
            As[kk + 3][m] = v.w;
        }
        {
            int k = tid >> 5;
            int n = (tid & 31) * 4;
            *(float4*)(&Bs[k][n]) = *(const float4*)(W + (k0 + k) * D + n);
        }
        __syncthreads();

        #pragma unroll
        for (int k = 0; k < 8; k++) {
            float a[8], b[8];
            #pragma unroll
            for (int i = 0; i < 8; i++) a[i] = As[k][ty * 8 + i];
            #pragma unroll
            for (int j = 0; j < 8; j++) b[j] = Bs[k][tx * 8 + j];
            #pragma unroll
            for (int i = 0; i < 8; i++)
                #pragma unroll
                for (int j = 0; j < 8; j++) acc[i][j] += a[i] * b[j];
        }
        __syncthreads();
    }

    #pragma unroll
    for (int i = 0; i < 8; i++) {
        int gr = row0 + ty * 8 + i;
        if (gr < M) {
            float4* o = (float4*)(Hout + gr * D + tx * 8);
            o[0] = make_float4(acc[i][0], acc[i][1], acc[i][2], acc[i][3]);
            o[1] = make_float4(acc[i][4], acc[i][5], acc[i][6], acc[i][7]);
        }
    }
}

// ---------------- half row gather helper ------------------------------------
__device__ __forceinline__ float4 ldrow_h(const __half* base, int row, int c4) {
    uint2 r = *(const uint2*)(base + (size_t)row * D + c4);
    __half2 a = *(__half2*)&r.x;
    __half2 b = *(__half2*)&r.y;
    float2 fa = __half22float2(a);
    float2 fb = __half22float2(b);
    return make_float4(fa.x, fa.y, fb.x, fb.y);
}

// ---------------- layer 1: fused aggregation + bias + ReLU + max(3) --------
__global__ void aggregate_l1_kernel(const float* __restrict__ bias0,
                                    const float* __restrict__ bias1,
                                    const float* __restrict__ bias2) {
    int grp  = threadIdx.x >> 5;
    int lane = threadIdx.x & 31;
    int node = blockIdx.x * 8 + grp;
    if (node >= N_NODES) return;
    int c4 = lane * 4;

    float4 best = make_float4(0.f, 0.f, 0.f, 0.f);
    #pragma unroll
    for (int t = 0; t < 3; t++) {
        const __half* Ht = g_Hh[t];
        const float* dv = g_dinv[t];
        const int* cols = g_col[t];
        const float* bp = (t == 0) ? bias0 : (t == 1) ? bias1 : bias2;
        float dn = dv[node];
        float4 self = ldrow_h(Ht, node, c4);
        float4 acc;
        acc.x = self.x * dn * dn; acc.y = self.y * dn * dn;
        acc.z = self.z * dn * dn; acc.w = self.w * dn * dn;

        int s = g_rowptr[t][node];
        int e = g_rowptr[t][node + 1];
        int k = s;
        for (; k + 4 <= e; k += 4) {
            int s0 = cols[k], s1 = cols[k + 1], s2 = cols[k + 2], s3 = cols[k + 3];
            float w0 = dv[s0] * dn, w1 = dv[s1] * dn, w2 = dv[s2] * dn, w3 = dv[s3] * dn;
            float4 v0 = ldrow_h(Ht, s0, c4);
            float4 v1 = ldrow_h(Ht, s1, c4);
            float4 v2 = ldrow_h(Ht, s2, c4);
            float4 v3 = ldrow_h(Ht, s3, c4);
            acc.x += v0.x * w0 + v1.x * w1 + v2.x * w2 + v3.x * w3;
            acc.y += v0.y * w0 + v1.y * w1 + v2.y * w2 + v3.y * w3;
            acc.z += v0.z * w0 + v1.z * w1 + v2.z * w2 + v3.z * w3;
            acc.w += v0.w * w0 + v1.w * w1 + v2.w * w2 + v3.w * w3;
        }
        for (; k < e; k++) {
            int s0 = cols[k];
            float w0 = dv[s0] * dn;
            float4 v0 = ldrow_h(Ht, s0, c4);
            acc.x += v0.x * w0; acc.y += v0.y * w0;
            acc.z += v0.z * w0; acc.w += v0.w * w0;
        }
        float4 b = *(const float4*)(bp + c4);
        best.x = fmaxf(best.x, fmaxf(acc.x + b.x, 0.f));
        best.y = fmaxf(best.y, fmaxf(acc.y + b.y, 0.f));
        best.z = fmaxf(best.z, fmaxf(acc.z + b.z, 0.f));
        best.w = fmaxf(best.w, fmaxf(acc.w + b.w, 0.f));
    }
    __half2 h01 = __floats2half2_rn(best.x, best.y);
    __half2 h23 = __floats2half2_rn(best.z, best.w);
    uint2 packed;
    packed.x = *(unsigned*)&h01;
    packed.y = *(unsigned*)&h23;
    *(uint2*)(g_Hcur + (size_t)node * D + c4) = packed;
}

// ---------------- layer 2: aggregate Hcur at the 4096 indexed nodes --------
__global__ void aggregate_l2_pre_kernel(const int* __restrict__ index) {
    int grp  = threadIdx.x >> 5;
    int lane = threadIdx.x & 31;
    int slot = blockIdx.x * 8 + grp;
    if (slot >= N_IDX) return;
    int node = index[slot];
    int c4 = lane * 4;

    float4 self = ldrow_h(g_Hcur, node, c4);
    #pragma unroll
    for (int t = 0; t < 3; t++) {
        const float* dv = g_dinv[t];
        const int* cols = g_col[t];
        float dn = dv[node];
        float4 acc;
        acc.x = self.x * dn * dn; acc.y = self.y * dn * dn;
        acc.z = self.z * dn * dn; acc.w = self.w * dn * dn;

        int s = g_rowptr[t][node];
        int e = g_rowptr[t][node + 1];
        int k = s;
        for (; k + 4 <= e; k += 4) {
            int s0 = cols[k], s1 = cols[k + 1], s2 = cols[k + 2], s3 = cols[k + 3];
            float w0 = dv[s0] * dn, w1 = dv[s1] * dn, w2 = dv[s2] * dn, w3 = dv[s3] * dn;
            float4 v0 = ldrow_h(g_Hcur, s0, c4);
            float4 v1 = ldrow_h(g_Hcur, s1, c4);
            float4 v2 = ldrow_h(g_Hcur, s2, c4);
            float4 v3 = ldrow_h(g_Hcur, s3, c4);
            acc.x += v0.x * w0 + v1.x * w1 + v2.x * w2 + v3.x * w3;
            acc.y += v0.y * w0 + v1.y * w1 + v2.y * w2 + v3.y * w3;
            acc.z += v0.z * w0 + v1.z * w1 + v2.z * w2 + v3.z * w3;
            acc.w += v0.w * w0 + v1.w * w1 + v2.w * w2 + v3.w * w3;
        }
        for (; k < e; k++) {
            int s0 = cols[k];
            float w0 = dv[s0] * dn;
            float4 v0 = ldrow_h(g_Hcur, s0, c4);
            acc.x += v0.x * w0; acc.y += v0.y * w0;
            acc.z += v0.z * w0; acc.w += v0.w * w0;
        }
        *(float4*)(g_A2[t] + (size_t)slot * D + c4) = acc;
    }
}

// ---------------- layer 2 epilogue: bias + ReLU + max(3) -> out -------------
__global__ void combine_l2_kernel(const float* __restrict__ bias0,
                                  const float* __restrict__ bias1,
                                  const float* __restrict__ bias2,
                                  float* __restrict__ out) {
    int idx = blockIdx.x * blockDim.x + threadIdx.x;   // over N_IDX * D
    int j = idx & (D - 1);
    float a = fmaxf(g_O2[0][idx] + bias0[j], 0.f);
    float b = fmaxf(g_O2[1][idx] + bias1[j], 0.f);
    float c = fmaxf(g_O2[2][idx] + bias2[j], 0.f);
    out[idx] = fmaxf(fmaxf(a, b), c);
}

// ---------------- launch ----------------------------------------------------
extern "C" void kernel_launch(void* const* d_in, const int* in_sizes, int n_in,
                              void* d_out, int out_size) {
    const float* x      = (const float*)d_in[0];
    const int*   e_syn  = (const int*)d_in[1];
    const int*   e_seq  = (const int*)d_in[2];
    const int*   e_sem  = (const int*)d_in[3];
    const int*   index  = (const int*)d_in[4];
    const float* w1_syn = (const float*)d_in[5];
    const float* b1_syn = (const float*)d_in[6];
    const float* w2_syn = (const float*)d_in[7];
    const float* b2_syn = (const float*)d_in[8];
    const float* w1_seq = (const float*)d_in[9];
    const float* b1_seq = (const float*)d_in[10];
    const float* w2_seq = (const float*)d_in[11];
    const float* b2_seq = (const float*)d_in[12];
    const float* w1_sem = (const float*)d_in[13];
    const float* b1_sem = (const float*)d_in[14];
    const float* w2_sem = (const float*)d_in[15];
    const float* b2_sem = (const float*)d_in[16];
    float* out = (float*)d_out;

    // one-time host resources (same graph structure every call)
    static cudaStream_t s_csr = nullptr;
    static cudaEvent_t ev_fork = nullptr, ev_join = nullptr;
    if (s_csr == nullptr) {
        cudaStreamCreateWithFlags(&s_csr, cudaStreamNonBlocking);
        cudaEventCreateWithFlags(&ev_fork, cudaEventDisableTiming);
        cudaEventCreateWithFlags(&ev_join, cudaEventDisableTiming);
    }

    // fork: CSR build on side stream, concurrent with the layer-1 GEMM
    cudaEventRecord(ev_fork, 0);
    cudaStreamWaitEvent(s_csr, ev_fork, 0);

    init_counts_kernel<<<(3 * N_NODES + 255) / 256, 256, 0, s_csr>>>();
    count_deg_kernel<<<(3 * N_EDGES + 255) / 256, 256, 0, s_csr>>>(e_syn, e_seq, e_sem);
    partial_sums_kernel<<<3 * NB, 256, 0, s_csr>>>();
    rowptr_final_kernel<<<3 * NB, 256, 0, s_csr>>>();
    scatter_edges_kernel<<<(3 * N_EDGES + 255) / 256, 256, 0, s_csr>>>(e_syn, e_seq, e_sem);

    // main stream: layer-1 tensor-core GEMMs (X and W conversions fused in)
    int gemm_grid = (N_NODES + 127) / 128;
    mma_gemm_kernel<<<dim3(gemm_grid, 3), 256>>>(x, w1_syn, w1_seq, w1_sem, N_NODES);

    // join
    cudaEventRecord(ev_join, s_csr);
    cudaStreamWaitEvent(0, ev_join, 0);

    aggregate_l1_kernel<<<(N_NODES + 7) / 8, 256>>>(b1_syn, b1_seq, b1_sem);

    // Layer 2: aggregate-then-GEMM (only 4096 rows through the GEMMs)
    aggregate_l2_pre_kernel<<<N_IDX / 8, 256>>>(index);
    gemm_small_kernel<<<dim3(N_IDX / 128, 3), 256>>>(w2_syn, w2_seq, w2_sem, N_IDX);

    combine_l2_kernel<<<(N_IDX * D) / 256, 256>>>(b2_syn, b2_seq, b2_sem, out);
}

// round 17
// speedup vs baseline: 1.0214x; 1.0214x over previous
#include <cuda_runtime.h>
#include <cuda_bf16.h>
#include <cuda_fp16.h>
#include <cstdint>
#include <math.h>

#define N_NODES 50000
#define N_EDGES 600000
#define D 128
#define N_IDX 4096
#define NB 196              // ceil(50000/256) blocks per edge type

// ---------------- scratch (static device allocations; no cudaMalloc) -------
__device__ __half g_Hh[3][N_NODES * D];   // per-branch layer-1 GEMM outputs (fp16)
__device__ __half g_Hcur[N_NODES * D];    // layer-1 combined features (fp16)
__device__ float g_A2[3][N_IDX * D];      // layer-2 aggregated inputs
__device__ float g_O2[3][N_IDX * D];      // layer-2 GEMM outputs
__device__ float g_dinv[3][N_NODES];
__device__ int   g_counts[3][N_NODES];    // zero at module load; self-cleaned each launch
__device__ int   g_rowptr[3][N_NODES + 1];
__device__ int   g_cursor[3][N_NODES];
__device__ int   g_col[3][N_EDGES];
__device__ int   g_bsum[3][NB];

// ---------------- CSR build (per-type kernels; 3 concurrent streams) --------
__global__ void count_deg_t_kernel(const int* __restrict__ ep, int t) {
    int e = blockIdx.x * blockDim.x + threadIdx.x;
    if (e >= N_EDGES) return;
    atomicAdd(&g_counts[t][ep[N_EDGES + e]], 1);
}

__global__ void partial_sums_t_kernel(int t) {
    int blk = blockIdx.x;
    int i   = blk * 256 + threadIdx.x;
    int v   = (i < N_NODES) ? g_counts[t][i] : 0;
    __shared__ int sh[256];
    sh[threadIdx.x] = v;
    __syncthreads();
    #pragma unroll
    for (int off = 128; off > 0; off >>= 1) {
        if (threadIdx.x < off) sh[threadIdx.x] += sh[threadIdx.x + off];
        __syncthreads();
    }
    if (threadIdx.x == 0) g_bsum[t][blk] = sh[0];
}

// block-offset + in-block scan -> rowptr/cursor/dinv; zeroes counts after use
__global__ void rowptr_final_t_kernel(int t) {
    int blk = blockIdx.x;
    int i   = blk * 256 + threadIdx.x;
    int v   = (i < N_NODES) ? g_counts[t][i] : 0;

    __shared__ int sh[256];
    __shared__ int red[256];

    int p = 0;
    for (int q = threadIdx.x; q < blk; q += 256) p += g_bsum[t][q];
    red[threadIdx.x] = p;
    sh[threadIdx.x] = v;
    __syncthreads();
    #pragma unroll
    for (int off = 128; off > 0; off >>= 1) {
        if (threadIdx.x < off) red[threadIdx.x] += red[threadIdx.x + off];
        __syncthreads();
    }
    int boff = red[0];

    #pragma unroll
    for (int off = 1; off < 256; off <<= 1) {
        int add = (threadIdx.x >= off) ? sh[threadIdx.x - off] : 0;
        __syncthreads();
        sh[threadIdx.x] += add;
        __syncthreads();
    }
    if (i < N_NODES) {
        int excl = boff + sh[threadIdx.x] - v;
        g_rowptr[t][i] = excl;
        g_cursor[t][i] = excl;
        g_dinv[t][i]   = rsqrtf((float)(v + 1));   // +1 self loop
        g_counts[t][i] = 0;                        // self-clean for next launch
    }
    if (blk == NB - 1 && threadIdx.x == 255) g_rowptr[t][N_NODES] = boff + sh[255];
}

__global__ void scatter_edges_t_kernel(const int* __restrict__ ep, int t) {
    int e = blockIdx.x * blockDim.x + threadIdx.x;
    if (e >= N_EDGES) return;
    int src = ep[e];
    int dst = ep[N_EDGES + e];
    int pos = atomicAdd(&g_cursor[t][dst], 1);
    g_col[t][pos] = src;
}

// ---------------- bf16 hi/lo split -------------------------------------------
__device__ __forceinline__ void split_bf16(float v, __nv_bfloat16& h, __nv_bfloat16& l) {
    h = __float2bfloat16(v);
    l = __float2bfloat16(v - __bfloat162float(h));
}

// ---------------- tensor-core GEMM: g_Hh[t] = X @ W[t] (bf16 split) ---------
__device__ __forceinline__ void ldsm_x4(unsigned* r, unsigned addr) {
    asm volatile("ldmatrix.sync.aligned.m8n8.x4.shared.b16 {%0,%1,%2,%3}, [%4];"
                 : "=r"(r[0]), "=r"(r[1]), "=r"(r[2]), "=r"(r[3]) : "r"(addr));
}
__device__ __forceinline__ void ldsm_x2t(unsigned* r, unsigned addr) {
    asm volatile("ldmatrix.sync.aligned.m8n8.x2.trans.shared.b16 {%0,%1}, [%2];"
                 : "=r"(r[0]), "=r"(r[1]) : "r"(addr));
}
__device__ __forceinline__ void mma_bf16(float* c, const unsigned* a, const unsigned* b) {
    asm volatile(
        "mma.sync.aligned.m16n8k16.row.col.f32.bf16.bf16.f32 "
        "{%0,%1,%2,%3}, {%4,%5,%6,%7}, {%8,%9}, {%0,%1,%2,%3};"
        : "+f"(c[0]), "+f"(c[1]), "+f"(c[2]), "+f"(c[3])
        : "r"(a[0]), "r"(a[1]), "r"(a[2]), "r"(a[3]), "r"(b[0]), "r"(b[1]));
}

__device__ __forceinline__ void split8_to_chunks(float4 va, float4 vb,
                                                 uint4& hp_out, uint4& lp_out) {
    __nv_bfloat16 h0,h1,h2,h3,h4,h5,h6,h7, l0,l1,l2,l3,l4,l5,l6,l7;
    split_bf16(va.x, h0, l0); split_bf16(va.y, h1, l1);
    split_bf16(va.z, h2, l2); split_bf16(va.w, h3, l3);
    split_bf16(vb.x, h4, l4); split_bf16(vb.y, h5, l5);
    split_bf16(vb.z, h6, l6); split_bf16(vb.w, h7, l7);
    __nv_bfloat162 hp[4] = { __halves2bfloat162(h0,h1), __halves2bfloat162(h2,h3),
                             __halves2bfloat162(h4,h5), __halves2bfloat162(h6,h7) };
    __nv_bfloat162 lp[4] = { __halves2bfloat162(l0,l1), __halves2bfloat162(l2,l3),
                             __halves2bfloat162(l4,l5), __halves2bfloat162(l6,l7) };
    hp_out = *(uint4*)hp;
    lp_out = *(uint4*)lp;
}

__global__ __launch_bounds__(256) void mma_gemm_kernel(const float* __restrict__ X,
                                                       const float* __restrict__ w0,
                                                       const float* __restrict__ w1,
                                                       const float* __restrict__ w2,
                                                       int M) {
    int t = blockIdx.y;
    const float* W = (t == 0) ? w0 : (t == 1) ? w1 : w2;
    __half* Hout = g_Hh[t];

    __shared__ __align__(16) unsigned char sA[128 * 128];
    __shared__ __align__(16) unsigned char sB[2][32 * 256];

    int tid = threadIdx.x;
    int lane = tid & 31, wid = tid >> 5;
    int wm = wid >> 2;
    int wn = wid & 3;
    int row0 = blockIdx.x * 128;

    unsigned sA_u  = (unsigned)__cvta_generic_to_shared(sA);
    unsigned sBh_u = (unsigned)__cvta_generic_to_shared(sB[0]);
    unsigned sBl_u = (unsigned)__cvta_generic_to_shared(sB[1]);

    float c[4][4][4];
    #pragma unroll
    for (int i = 0; i < 4; i++)
        #pragma unroll
        for (int j = 0; j < 4; j++)
            #pragma unroll
            for (int q = 0; q < 4; q++) c[i][j][q] = 0.f;

    for (int kc = 0; kc < 4; kc++) {
        // fused A load+convert
        #pragma unroll
        for (int i = 0; i < 2; i++) {
            int cid = tid + i * 256;           // 0..511
            int r = cid >> 2, q = cid & 3;     // row 0..127, col-group 0..3
            int gr = row0 + r;
            float4 va = make_float4(0.f, 0.f, 0.f, 0.f);
            float4 vb = make_float4(0.f, 0.f, 0.f, 0.f);
            if (gr < M) {
                const float* xp = X + (size_t)gr * D + kc * 32 + q * 8;
                va = *(const float4*)xp;
                vb = *(const float4*)(xp + 4);
            }
            uint4 hp, lp;
            split8_to_chunks(va, vb, hp, lp);
            *(uint4*)(sA + r * 128 + ((q ^ (r & 7)) << 4))       = hp;
            *(uint4*)(sA + r * 128 + (((q + 4) ^ (r & 7)) << 4)) = lp;
        }
        // fused B load+convert
        #pragma unroll
        for (int i = 0; i < 2; i++) {
            int cid = tid + i * 256;           // 0..511
            int k = cid >> 4, ch = cid & 15;   // k-row 0..31, chunk 0..15
            const float* wp = W + (size_t)(kc * 32 + k) * D + ch * 8;
            float4 va = *(const float4*)wp;
            float4 vb = *(const float4*)(wp + 4);
            uint4 hp, lp;
            split8_to_chunks(va, vb, hp, lp);
            unsigned off = k * 256 + ((ch ^ (k & 7)) << 4);
            *(uint4*)(sB[0] + off) = hp;
            *(uint4*)(sB[1] + off) = lp;
        }
        __syncthreads();

        #pragma unroll
        for (int ks = 0; ks < 2; ks++) {
            unsigned ah[4][4], al[4][4], bh[4][2], bl[4][2];
            #pragma unroll
            for (int mf = 0; mf < 4; mf++) {
                int mr = wm * 64 + mf * 16 + (lane & 7) + ((lane >> 3) & 1) * 8;
                int lc = ks * 2 + (lane >> 4);
                ldsm_x4(ah[mf], sA_u + mr * 128 + ((lc ^ (mr & 7)) << 4));
                ldsm_x4(al[mf], sA_u + mr * 128 + (((lc + 4) ^ (mr & 7)) << 4));
            }
            #pragma unroll
            for (int nf = 0; nf < 4; nf++) {
                int kk = ks * 16 + (lane & 7) + ((lane >> 3) & 1) * 8;
                int gc = wn * 4 + nf;
                unsigned off = kk * 256 + ((gc ^ (kk & 7)) << 4);
                ldsm_x2t(bh[nf], sBh_u + off);
                ldsm_x2t(bl[nf], sBl_u + off);
            }
            #pragma unroll
            for (int mf = 0; mf < 4; mf++)
                #pragma unroll
                for (int nf = 0; nf < 4; nf++) {
                    mma_bf16(c[mf][nf], ah[mf], bh[nf]);
                    mma_bf16(c[mf][nf], ah[mf], bl[nf]);
                    mma_bf16(c[mf][nf], al[mf], bh[nf]);
                }
        }
        __syncthreads();
    }

    // store accumulators as fp16
    int g = lane >> 2, tq = lane & 3;
    #pragma unroll
    for (int mf = 0; mf < 4; mf++) {
        int r0 = row0 + wm * 64 + mf * 16 + g;
        int r1 = r0 + 8;
        #pragma unroll
        for (int nf = 0; nf < 4; nf++) {
            int cb = wn * 32 + nf * 8 + tq * 2;
            if (r0 < M) *(__half2*)(Hout + (size_t)r0 * D + cb) = __floats2half2_rn(c[mf][nf][0], c[mf][nf][1]);
            if (r1 < M) *(__half2*)(Hout + (size_t)r1 * D + cb) = __floats2half2_rn(c[mf][nf][2], c[mf][nf][3]);
        }
    }
}

// ---------------- FFMA GEMM for small layer-2 matrices (per-branch grid.y) --
__global__ void gemm_small_kernel(const float* __restrict__ w0,
                                  const float* __restrict__ w1,
                                  const float* __restrict__ w2, int M) {
    int t = blockIdx.y;
    const float* X = g_A2[t];
    const float* W = (t == 0) ? w0 : (t == 1) ? w1 : w2;
    float* Hout = g_O2[t];

    __shared__ float As[8][128];
    __shared__ float Bs[8][128];

    int tid  = threadIdx.x;
    int row0 = blockIdx.x * 128;
    int tx = tid & 15;
    int ty = tid >> 4;

    float acc[8][8];
    #pragma unroll
    for (int i = 0; i < 8; i++)
        #pragma unroll
        for (int j = 0; j < 8; j++) acc[i][j] = 0.f;

    for (int k0 = 0; k0 < 128; k0 += 8) {
        {
            int m  = tid >> 1;
            int kk = (tid & 1) * 4;
            int gr = row0 + m;
            float4 v = make_float4(0.f, 0.f, 0.f, 0.f);
            if (gr < M) v = *(const float4*)(X + gr * D + k0 + kk);
            As[kk + 0][m] = v.x;
            As[kk + 1][m] = v.y;
            As[kk + 2][m] = v.z;
            As[kk + 3][m] = v.w;
        }
        {
            int k = tid >> 5;
            int n = (tid & 31) * 4;
            *(float4*)(&Bs[k][n]) = *(const float4*)(W + (k0 + k) * D + n);
        }
        __syncthreads();

        #pragma unroll
        for (int k = 0; k < 8; k++) {
            float a[8], b[8];
            #pragma unroll
            for (int i = 0; i < 8; i++) a[i] = As[k][ty * 8 + i];
            #pragma unroll
            for (int j = 0; j < 8; j++) b[j] = Bs[k][tx * 8 + j];
            #pragma unroll
            for (int i = 0; i < 8; i++)
                #pragma unroll
                for (int j = 0; j < 8; j++) acc[i][j] += a[i] * b[j];
        }
        __syncthreads();
    }

    #pragma unroll
    for (int i = 0; i < 8; i++) {
        int gr = row0 + ty * 8 + i;
        if (gr < M) {
            float4* o = (float4*)(Hout + gr * D + tx * 8);
            o[0] = make_float4(acc[i][0], acc[i][1], acc[i][2], acc[i][3]);
            o[1] = make_float4(acc[i][4], acc[i][5], acc[i][6], acc[i][7]);
        }
    }
}

// ---------------- half row gather helper ------------------------------------
__device__ __forceinline__ float4 ldrow_h(const __half* base, int row, int c4) {
    uint2 r = *(const uint2*)(base + (size_t)row * D + c4);
    __half2 a = *(__half2*)&r.x;
    __half2 b = *(__half2*)&r.y;
    float2 fa = __half22float2(a);
    float2 fb = __half22float2(b);
    return make_float4(fa.x, fa.y, fb.x, fb.y);
}

// ---------------- layer 1: fused aggregation + bias + ReLU + max(3) --------
__global__ void aggregate_l1_kernel(const float* __restrict__ bias0,
                                    const float* __restrict__ bias1,
                                    const float* __restrict__ bias2) {
    int grp  = threadIdx.x >> 5;
    int lane = threadIdx.x & 31;
    int node = blockIdx.x * 8 + grp;
    if (node >= N_NODES) return;
    int c4 = lane * 4;

    float4 best = make_float4(0.f, 0.f, 0.f, 0.f);
    #pragma unroll
    for (int t = 0; t < 3; t++) {
        const __half* Ht = g_Hh[t];
        const float* dv = g_dinv[t];
        const int* cols = g_col[t];
        const float* bp = (t == 0) ? bias0 : (t == 1) ? bias1 : bias2;
        float dn = dv[node];
        float4 self = ldrow_h(Ht, node, c4);
        float4 acc;
        acc.x = self.x * dn * dn; acc.y = self.y * dn * dn;
        acc.z = self.z * dn * dn; acc.w = self.w * dn * dn;

        int s = g_rowptr[t][node];
        int e = g_rowptr[t][node + 1];
        int k = s;
        for (; k + 4 <= e; k += 4) {
            int s0 = cols[k], s1 = cols[k + 1], s2 = cols[k + 2], s3 = cols[k + 3];
            float w0 = dv[s0] * dn, w1 = dv[s1] * dn, w2 = dv[s2] * dn, w3 = dv[s3] * dn;
            float4 v0 = ldrow_h(Ht, s0, c4);
            float4 v1 = ldrow_h(Ht, s1, c4);
            float4 v2 = ldrow_h(Ht, s2, c4);
            float4 v3 = ldrow_h(Ht, s3, c4);
            acc.x += v0.x * w0 + v1.x * w1 + v2.x * w2 + v3.x * w3;
            acc.y += v0.y * w0 + v1.y * w1 + v2.y * w2 + v3.y * w3;
            acc.z += v0.z * w0 + v1.z * w1 + v2.z * w2 + v3.z * w3;
            acc.w += v0.w * w0 + v1.w * w1 + v2.w * w2 + v3.w * w3;
        }
        for (; k < e; k++) {
            int s0 = cols[k];
            float w0 = dv[s0] * dn;
            float4 v0 = ldrow_h(Ht, s0, c4);
            acc.x += v0.x * w0; acc.y += v0.y * w0;
            acc.z += v0.z * w0; acc.w += v0.w * w0;
        }
        float4 b = *(const float4*)(bp + c4);
        best.x = fmaxf(best.x, fmaxf(acc.x + b.x, 0.f));
        best.y = fmaxf(best.y, fmaxf(acc.y + b.y, 0.f));
        best.z = fmaxf(best.z, fmaxf(acc.z + b.z, 0.f));
        best.w = fmaxf(best.w, fmaxf(acc.w + b.w, 0.f));
    }
    __half2 h01 = __floats2half2_rn(best.x, best.y);
    __half2 h23 = __floats2half2_rn(best.z, best.w);
    uint2 packed;
    packed.x = *(unsigned*)&h01;
    packed.y = *(unsigned*)&h23;
    *(uint2*)(g_Hcur + (size_t)node * D + c4) = packed;
}

// ---------------- layer 2: aggregate Hcur at the 4096 indexed nodes --------
__global__ void aggregate_l2_pre_kernel(const int* __restrict__ index) {
    int grp  = threadIdx.x >> 5;
    int lane = threadIdx.x & 31;
    int slot = blockIdx.x * 8 + grp;
    if (slot >= N_IDX) return;
    int node = index[slot];
    int c4 = lane * 4;

    float4 self = ldrow_h(g_Hcur, node, c4);
    #pragma unroll
    for (int t = 0; t < 3; t++) {
        const float* dv = g_dinv[t];
        const int* cols = g_col[t];
        float dn = dv[node];
        float4 acc;
        acc.x = self.x * dn * dn; acc.y = self.y * dn * dn;
        acc.z = self.z * dn * dn; acc.w = self.w * dn * dn;

        int s = g_rowptr[t][node];
        int e = g_rowptr[t][node + 1];
        int k = s;
        for (; k + 4 <= e; k += 4) {
            int s0 = cols[k], s1 = cols[k + 1], s2 = cols[k + 2], s3 = cols[k + 3];
            float w0 = dv[s0] * dn, w1 = dv[s1] * dn, w2 = dv[s2] * dn, w3 = dv[s3] * dn;
            float4 v0 = ldrow_h(g_Hcur, s0, c4);
            float4 v1 = ldrow_h(g_Hcur, s1, c4);
            float4 v2 = ldrow_h(g_Hcur, s2, c4);
            float4 v3 = ldrow_h(g_Hcur, s3, c4);
            acc.x += v0.x * w0 + v1.x * w1 + v2.x * w2 + v3.x * w3;
            acc.y += v0.y * w0 + v1.y * w1 + v2.y * w2 + v3.y * w3;
            acc.z += v0.z * w0 + v1.z * w1 + v2.z * w2 + v3.z * w3;
            acc.w += v0.w * w0 + v1.w * w1 + v2.w * w2 + v3.w * w3;
        }
        for (; k < e; k++) {
            int s0 = cols[k];
            float w0 = dv[s0] * dn;
            float4 v0 = ldrow_h(g_Hcur, s0, c4);
            acc.x += v0.x * w0; acc.y += v0.y * w0;
            acc.z += v0.z * w0; acc.w += v0.w * w0;
        }
        *(float4*)(g_A2[t] + (size_t)slot * D + c4) = acc;
    }
}

// ---------------- layer 2 epilogue: bias + ReLU + max(3) -> out -------------
__global__ void combine_l2_kernel(const float* __restrict__ bias0,
                                  const float* __restrict__ bias1,
                                  const float* __restrict__ bias2,
                                  float* __restrict__ out) {
    int idx = blockIdx.x * blockDim.x + threadIdx.x;   // over N_IDX * D
    int j = idx & (D - 1);
    float a = fmaxf(g_O2[0][idx] + bias0[j], 0.f);
    float b = fmaxf(g_O2[1][idx] + bias1[j], 0.f);
    float c = fmaxf(g_O2[2][idx] + bias2[j], 0.f);
    out[idx] = fmaxf(fmaxf(a, b), c);
}

// ---------------- launch ----------------------------------------------------
extern "C" void kernel_launch(void* const* d_in, const int* in_sizes, int n_in,
                              void* d_out, int out_size) {
    const float* x      = (const float*)d_in[0];
    const int*   e_syn  = (const int*)d_in[1];
    const int*   e_seq  = (const int*)d_in[2];
    const int*   e_sem  = (const int*)d_in[3];
    const int*   index  = (const int*)d_in[4];
    const float* w1_syn = (const float*)d_in[5];
    const float* b1_syn = (const float*)d_in[6];
    const float* w2_syn = (const float*)d_in[7];
    const float* b2_syn = (const float*)d_in[8];
    const float* w1_seq = (const float*)d_in[9];
    const float* b1_seq = (const float*)d_in[10];
    const float* w2_seq = (const float*)d_in[11];
    const float* b2_seq = (const float*)d_in[12];
    const float* w1_sem = (const float*)d_in[13];
    const float* b1_sem = (const float*)d_in[14];
    const float* w2_sem = (const float*)d_in[15];
    const float* b2_sem = (const float*)d_in[16];
    float* out = (float*)d_out;

    // one-time host resources (same graph structure every call)
    static cudaStream_t s_t[3] = {nullptr, nullptr, nullptr};
    static cudaEvent_t ev_fork = nullptr;
    static cudaEvent_t ev_done[3] = {nullptr, nullptr, nullptr};
    if (s_t[0] == nullptr) {
        for (int t = 0; t < 3; t++) {
            cudaStreamCreateWithFlags(&s_t[t], cudaStreamNonBlocking);
            cudaEventCreateWithFlags(&ev_done[t], cudaEventDisableTiming);
        }
        cudaEventCreateWithFlags(&ev_fork, cudaEventDisableTiming);
    }

    const int* eptr[3] = {e_syn, e_seq, e_sem};

    // fork: 3 per-type CSR chains, concurrent with each other and the GEMM
    cudaEventRecord(ev_fork, 0);
    int edge_grid = (N_EDGES + 255) / 256;
    for (int t = 0; t < 3; t++) {
        cudaStreamWaitEvent(s_t[t], ev_fork, 0);
        count_deg_t_kernel<<<edge_grid, 256, 0, s_t[t]>>>(eptr[t], t);
        partial_sums_t_kernel<<<NB, 256, 0, s_t[t]>>>(t);
        rowptr_final_t_kernel<<<NB, 256, 0, s_t[t]>>>(t);
        scatter_edges_t_kernel<<<edge_grid, 256, 0, s_t[t]>>>(eptr[t], t);
        cudaEventRecord(ev_done[t], s_t[t]);
    }

    // main stream: layer-1 tensor-core GEMMs (X and W conversions fused in)
    int gemm_grid = (N_NODES + 127) / 128;
    mma_gemm_kernel<<<dim3(gemm_grid, 3), 256>>>(x, w1_syn, w1_seq, w1_sem, N_NODES);

    // join all three CSR streams
    for (int t = 0; t < 3; t++) cudaStreamWaitEvent(0, ev_done[t], 0);

    aggregate_l1_kernel<<<(N_NODES + 7) / 8, 256>>>(b1_syn, b1_seq, b1_sem);

    // Layer 2: aggregate-then-GEMM (only 4096 rows through the GEMMs)
    aggregate_l2_pre_kernel<<<N_IDX / 8, 256>>>(index);
    gemm_small_kernel<<<dim3(N_IDX / 128, 3), 256>>>(w2_syn, w2_seq, w2_sem, N_IDX);

    combine_l2_kernel<<<(N_IDX * D) / 256, 256>>>(b2_syn, b2_seq, b2_sem, out);
}